// round 1
// baseline (speedup 1.0000x reference)
#include <cuda_runtime.h>
#include <math.h>

#define NROWS 8192
#define NCOLS 8192
#define RB 32
#define CB 32
#define HID 100
#define ROWS_PER_CTA 128
#define THREADS_RED 256
#define STRIP_COLS (THREADS_RED * 4)   // 1024 columns per CTA strip

// Global scratch for block sums (device global: no allocation APIs allowed).
__device__ float g_blk[RB * CB];

// ---------------------------------------------------------------------------
// Kernel 0: zero the scratch accumulator (must happen every graph replay).
// ---------------------------------------------------------------------------
__global__ void mar_zero_kernel() {
    int i = threadIdx.x;
    if (i < RB * CB) g_blk[i] = 0.0f;
}

// ---------------------------------------------------------------------------
// Kernel 1: segmented block-sum reduce of X.
// Grid: (NCOLS/STRIP_COLS, NROWS/ROWS_PER_CTA) = (8, 64), 256 threads.
// Each thread owns 4 fixed contiguous columns; accumulates down rows in
// registers, flushing to shared [32][32] only when the (sorted, CTA-uniform)
// row segment id changes. CTA-end: merge nonzero bins to global via atomics.
// ---------------------------------------------------------------------------
__global__ __launch_bounds__(THREADS_RED)
void mar_reduce_kernel(const float* __restrict__ X,
                       const int* __restrict__ row_ids,
                       const int* __restrict__ col_ids) {
    __shared__ float s_blk[RB * CB];
    __shared__ unsigned char s_rseg[ROWS_PER_CTA];

    const int tid = threadIdx.x;
    const int strip = blockIdx.x;           // column strip
    const int rchunk = blockIdx.y;          // row chunk
    const int r0 = rchunk * ROWS_PER_CTA;
    const int c0 = strip * STRIP_COLS + tid * 4;

    // Zero shared accumulator
    for (int i = tid; i < RB * CB; i += THREADS_RED) s_blk[i] = 0.0f;
    // Stage row segment ids for this chunk (values 0..31 fit in u8)
    for (int i = tid; i < ROWS_PER_CTA; i += THREADS_RED)
        s_rseg[i] = (unsigned char)row_ids[r0 + i];

    // Fixed column segment ids for this thread's 4 columns
    const int cs0 = col_ids[c0 + 0];
    const int cs1 = col_ids[c0 + 1];
    const int cs2 = col_ids[c0 + 2];
    const int cs3 = col_ids[c0 + 3];

    __syncthreads();

    const float4* __restrict__ p =
        (const float4*)(X + (size_t)r0 * NCOLS + c0);
    const int row_stride_v4 = NCOLS / 4;    // 2048 float4 per row

    float a0 = 0.f, a1 = 0.f, a2 = 0.f, a3 = 0.f;
    int cur = s_rseg[0];

#pragma unroll 4
    for (int r = 0; r < ROWS_PER_CTA; r++) {
        int rid = s_rseg[r];
        if (rid != cur) {                    // CTA-uniform branch (sorted ids)
            int base = cur * CB;
            atomicAdd(&s_blk[base + cs0], a0);
            atomicAdd(&s_blk[base + cs1], a1);
            atomicAdd(&s_blk[base + cs2], a2);
            atomicAdd(&s_blk[base + cs3], a3);
            a0 = a1 = a2 = a3 = 0.f;
            cur = rid;
        }
        float4 v = p[(size_t)r * row_stride_v4];
        a0 += v.x; a1 += v.y; a2 += v.z; a3 += v.w;
    }
    {   // final flush
        int base = cur * CB;
        atomicAdd(&s_blk[base + cs0], a0);
        atomicAdd(&s_blk[base + cs1], a1);
        atomicAdd(&s_blk[base + cs2], a2);
        atomicAdd(&s_blk[base + cs3], a3);
    }
    __syncthreads();

    // Merge only nonzero bins to global (a CTA touches ~2 row segs x ~2 col segs)
    for (int i = tid; i < RB * CB; i += THREADS_RED) {
        float v = s_blk[i];
        if (v != 0.0f) atomicAdd(&g_blk[i], v);
    }
}

// ---------------------------------------------------------------------------
// Kernel 2: cumsums (binary search on sorted ids), block mean, 3-layer MLP,
// sigmoid, pack output: [propensity 1024][row_cumsum 33][col_cumsum 33] f32.
// Single block, 1024 threads.
// ---------------------------------------------------------------------------
__device__ __forceinline__ int lb_count_less(const int* __restrict__ a,
                                             int n, int key) {
    int lo = 0, hi = n;
    while (lo < hi) {
        int mid = (lo + hi) >> 1;
        if (a[mid] < key) lo = mid + 1; else hi = mid;
    }
    return lo;
}

__global__ __launch_bounds__(1024)
void mar_finalize_kernel(const int* __restrict__ row_ids,
                         const int* __restrict__ col_ids,
                         const float* __restrict__ W1, const float* __restrict__ b1,
                         const float* __restrict__ W2, const float* __restrict__ b2,
                         const float* __restrict__ W3, const float* __restrict__ b3,
                         float* __restrict__ out) {
    __shared__ float s_x[RB * CB];     // block means (MLP input, 1024)
    __shared__ float s_h1[HID];
    __shared__ float s_h2[HID];
    __shared__ int s_rcum[RB + 1];
    __shared__ int s_ccum[CB + 1];

    const int tid = threadIdx.x;

    // Exact cumsums via lower_bound on the sorted segment ids
    if (tid <= RB)        s_rcum[tid] = lb_count_less(row_ids, NROWS, tid);
    else if (tid < 2 * (RB + 1)) {
        int t = tid - (RB + 1);
        s_ccum[t] = lb_count_less(col_ids, NCOLS, t);
    }
    __syncthreads();

    // Block mean = blk_sum / max(rcnt*ccnt, 1)
    if (tid < RB * CB) {
        int ri = tid >> 5, ci = tid & 31;
        float rc = (float)(s_rcum[ri + 1] - s_rcum[ri]);
        float cc = (float)(s_ccum[ci + 1] - s_ccum[ci]);
        float cnt = fmaxf(rc * cc, 1.0f);
        s_x[tid] = g_blk[tid] / cnt;
    }
    // Init h1 with bias
    if (tid < HID) s_h1[tid] = b1[tid];
    __syncthreads();

    // Layer 1: h1[k] = relu( sum_i x[i] * W1[i][k] + b1[k] ), i in [0,1024)
    // 8 chunks x 128 k-lanes (k<100 active): 128-load chain per thread.
    {
        int chunk = tid >> 7;       // 0..7
        int k = tid & 127;          // coalesced over k
        if (k < HID) {
            float s = 0.0f;
            int i0 = chunk * 128;
            const float* w = W1 + (size_t)i0 * HID + k;
#pragma unroll 8
            for (int i = 0; i < 128; i++)
                s += s_x[i0 + i] * w[(size_t)i * HID];
            atomicAdd(&s_h1[k], s);
        }
    }
    __syncthreads();
    if (tid < HID) s_h1[tid] = fmaxf(s_h1[tid], 0.0f);
    __syncthreads();

    // Layer 2: h2[k] = relu( h1 @ W2[:,k] + b2[k] ), 100x100
    if (tid < HID) {
        float s = b2[tid];
        const float* w = W2 + tid;
#pragma unroll 4
        for (int i = 0; i < HID; i++)
            s += s_h1[i] * w[(size_t)i * HID];
        s_h2[tid] = fmaxf(s, 0.0f);
    }
    __syncthreads();

    // Layer 3: out[j] = sigmoid( h2 @ W3[:,j] + b3[j] ), j in [0,1024)
    if (tid < RB * CB) {
        float s = b3[tid];
        const float* w = W3 + tid;
#pragma unroll 4
        for (int i = 0; i < HID; i++)
            s += s_h2[i] * w[(size_t)i * (RB * CB)];
        out[tid] = 1.0f / (1.0f + expf(-s));
    }

    // Pack cumsums (as f32) after the 1024 propensity values
    if (tid <= RB)  out[RB * CB + tid] = (float)s_rcum[tid];
    if (tid <= CB)  out[RB * CB + (RB + 1) + tid] = (float)s_ccum[tid];
}

// ---------------------------------------------------------------------------
// Launch
// ---------------------------------------------------------------------------
extern "C" void kernel_launch(void* const* d_in, const int* in_sizes, int n_in,
                              void* d_out, int out_size) {
    const float* X       = (const float*)d_in[0];
    const int*   row_ids = (const int*)d_in[1];
    const int*   col_ids = (const int*)d_in[2];
    const float* W1 = (const float*)d_in[3];
    const float* b1 = (const float*)d_in[4];
    const float* W2 = (const float*)d_in[5];
    const float* b2 = (const float*)d_in[6];
    const float* W3 = (const float*)d_in[7];
    const float* b3 = (const float*)d_in[8];
    float* out = (float*)d_out;

    mar_zero_kernel<<<1, 1024>>>();

    dim3 grid(NCOLS / STRIP_COLS, NROWS / ROWS_PER_CTA);   // (8, 64)
    mar_reduce_kernel<<<grid, THREADS_RED>>>(X, row_ids, col_ids);

    mar_finalize_kernel<<<1, 1024>>>(row_ids, col_ids,
                                     W1, b1, W2, b2, W3, b3, out);
}

// round 3
// speedup vs baseline: 1.2276x; 1.2276x over previous
#include <cuda_runtime.h>
#include <math.h>

#define NROWS 8192
#define NCOLS 8192
#define RB 32
#define CB 32
#define HID 100
#define ROWS_PER_CTA 128
#define THREADS_RED 128
#define STRIP_COLS (THREADS_RED * 4)   // 512 columns per CTA strip
#define ST_V4 (NCOLS / 4)              // float4 row stride
#define MAXRUNS 33

// Global scratch for block sums. Zero-initialized at module load; the
// finalize kernel re-zeroes it after reading, so every graph replay sees
// a clean accumulator (deterministic, no zero kernel needed).
__device__ float g_blk[RB * CB];

// ---------------------------------------------------------------------------
// Kernel 1: segmented block-sum reduce of X.
// Grid: (NCOLS/STRIP_COLS, NROWS/ROWS_PER_CTA) = (16, 64) = 1024 CTAs.
// Row-segment RUNS are precomputed (sorted ids -> few runs), so the hot loop
// is branch-free with 8 front-batched float4 loads per iteration (MLP ~ 8).
// ---------------------------------------------------------------------------
__global__ __launch_bounds__(THREADS_RED)
void mar_reduce_kernel(const float* __restrict__ X,
                       const int* __restrict__ row_ids,
                       const int* __restrict__ col_ids) {
    __shared__ float s_blk[RB * CB];
    __shared__ unsigned char s_rseg[ROWS_PER_CTA];
    __shared__ short s_run_start[MAXRUNS + 1];
    __shared__ unsigned char s_run_seg[MAXRUNS];
    __shared__ int s_nrun;

    const int tid = threadIdx.x;
    const int r0 = blockIdx.y * ROWS_PER_CTA;
    const int c0 = blockIdx.x * STRIP_COLS + tid * 4;

    // Zero shared accumulator; stage row segment ids for this chunk.
    for (int i = tid; i < RB * CB; i += THREADS_RED) s_blk[i] = 0.0f;
    if (tid < ROWS_PER_CTA)
        s_rseg[tid] = (unsigned char)row_ids[r0 + tid];

    // Fixed column segment ids for this thread's 4 columns.
    const int cs0 = col_ids[c0 + 0];
    const int cs1 = col_ids[c0 + 1];
    const int cs2 = col_ids[c0 + 2];
    const int cs3 = col_ids[c0 + 3];
    __syncthreads();

    // Build run list (sorted ids -> at most 32 runs; typically 1-2).
    if (tid == 0) {
        int n = 0;
        int prev = -1;
        for (int r = 0; r < ROWS_PER_CTA; r++) {
            int s = s_rseg[r];
            if (s != prev) {
                s_run_start[n] = (short)r;
                s_run_seg[n] = (unsigned char)s;
                n++; prev = s;
            }
        }
        s_run_start[n] = ROWS_PER_CTA;
        s_nrun = n;
    }
    __syncthreads();

    const float4* __restrict__ p = (const float4*)(X + (size_t)r0 * NCOLS + c0);
    const int nrun = s_nrun;

    for (int run = 0; run < nrun; run++) {
        const int rs = s_run_start[run];
        const int re = s_run_start[run + 1];
        const int seg = s_run_seg[run];
        const float4* __restrict__ q = p + (size_t)rs * ST_V4;
        const int n = re - rs;

        float a0 = 0.f, a1 = 0.f, a2 = 0.f, a3 = 0.f;
        int r = 0;
        // Branch-free main loop: 8 independent float4 loads batched up front.
        for (; r + 8 <= n; r += 8) {
            float4 v0 = q[(size_t)(r + 0) * ST_V4];
            float4 v1 = q[(size_t)(r + 1) * ST_V4];
            float4 v2 = q[(size_t)(r + 2) * ST_V4];
            float4 v3 = q[(size_t)(r + 3) * ST_V4];
            float4 v4 = q[(size_t)(r + 4) * ST_V4];
            float4 v5 = q[(size_t)(r + 5) * ST_V4];
            float4 v6 = q[(size_t)(r + 6) * ST_V4];
            float4 v7 = q[(size_t)(r + 7) * ST_V4];
            a0 += v0.x; a1 += v0.y; a2 += v0.z; a3 += v0.w;
            a0 += v1.x; a1 += v1.y; a2 += v1.z; a3 += v1.w;
            a0 += v2.x; a1 += v2.y; a2 += v2.z; a3 += v2.w;
            a0 += v3.x; a1 += v3.y; a2 += v3.z; a3 += v3.w;
            a0 += v4.x; a1 += v4.y; a2 += v4.z; a3 += v4.w;
            a0 += v5.x; a1 += v5.y; a2 += v5.z; a3 += v5.w;
            a0 += v6.x; a1 += v6.y; a2 += v6.z; a3 += v6.w;
            a0 += v7.x; a1 += v7.y; a2 += v7.z; a3 += v7.w;
        }
        for (; r < n; r++) {
            float4 v = q[(size_t)r * ST_V4];
            a0 += v.x; a1 += v.y; a2 += v.z; a3 += v.w;
        }
        const int base = seg * CB;
        atomicAdd(&s_blk[base + cs0], a0);
        atomicAdd(&s_blk[base + cs1], a1);
        atomicAdd(&s_blk[base + cs2], a2);
        atomicAdd(&s_blk[base + cs3], a3);
    }
    __syncthreads();

    // Merge only nonzero bins to global (a CTA touches only a few bins).
    for (int i = tid; i < RB * CB; i += THREADS_RED) {
        float v = s_blk[i];
        if (v != 0.0f) atomicAdd(&g_blk[i], v);
    }
}

// ---------------------------------------------------------------------------
// Kernel 2: cumsums (binary search on sorted ids), block mean, 3-layer MLP,
// sigmoid, pack output. Also re-zeroes g_blk for the next graph replay.
// Single block, 1024 threads.
// ---------------------------------------------------------------------------
__device__ __forceinline__ int lb_count_less(const int* __restrict__ a,
                                             int n, int key) {
    int lo = 0, hi = n;
    while (lo < hi) {
        int mid = (lo + hi) >> 1;
        if (__ldg(&a[mid]) < key) lo = mid + 1; else hi = mid;
    }
    return lo;
}

__global__ __launch_bounds__(1024)
void mar_finalize_kernel(const int* __restrict__ row_ids,
                         const int* __restrict__ col_ids,
                         const float* __restrict__ W1, const float* __restrict__ b1,
                         const float* __restrict__ W2, const float* __restrict__ b2,
                         const float* __restrict__ W3, const float* __restrict__ b3,
                         float* __restrict__ out) {
    __shared__ float s_x[RB * CB];     // block means (MLP input, 1024)
    __shared__ float s_h1[HID];
    __shared__ float s_h2[HID];
    __shared__ int s_rcum[RB + 1];
    __shared__ int s_ccum[CB + 1];

    const int tid = threadIdx.x;

    // Exact cumsums via lower_bound on the sorted segment ids.
    if (tid <= RB) s_rcum[tid] = lb_count_less(row_ids, NROWS, tid);
    else if (tid < 2 * (RB + 1)) {
        int t = tid - (RB + 1);
        s_ccum[t] = lb_count_less(col_ids, NCOLS, t);
    }
    __syncthreads();

    // Block mean = blk_sum / max(rcnt*ccnt, 1)
    {
        int ri = tid >> 5, ci = tid & 31;
        float rc = (float)(s_rcum[ri + 1] - s_rcum[ri]);
        float cc = (float)(s_ccum[ci + 1] - s_ccum[ci]);
        float cnt = fmaxf(rc * cc, 1.0f);
        s_x[tid] = g_blk[tid] / cnt;
    }
    if (tid < HID) s_h1[tid] = b1[tid];
    __syncthreads();

    // Self-clean the accumulator for the next graph replay.
    // Safe: this thread already consumed g_blk[tid] above (same-thread order).
    g_blk[tid] = 0.0f;

    // Layer 1: h1[k] = relu( sum_i x[i] * W1[i][k] + b1[k] ), i in [0,1024).
    // 8 chunks x 128 k-lanes (k<100 active); coalesced over k; unroll 16.
    {
        int chunk = tid >> 7;       // 0..7
        int k = tid & 127;
        if (k < HID) {
            float s = 0.0f;
            int i0 = chunk * 128;
            const float* w = W1 + (size_t)i0 * HID + k;
#pragma unroll 16
            for (int i = 0; i < 128; i++)
                s += s_x[i0 + i] * __ldg(&w[(size_t)i * HID]);
            atomicAdd(&s_h1[k], s);
        }
    }
    __syncthreads();
    if (tid < HID) s_h1[tid] = fmaxf(s_h1[tid], 0.0f);
    __syncthreads();

    // Layer 2: h2[k] = relu( h1 @ W2[:,k] + b2[k] ), 100x100.
    if (tid < HID) {
        float s = b2[tid];
        const float* w = W2 + tid;
#pragma unroll 20
        for (int i = 0; i < HID; i++)
            s += s_h1[i] * __ldg(&w[(size_t)i * HID]);
        s_h2[tid] = fmaxf(s, 0.0f);
    }
    __syncthreads();

    // Layer 3: out[j] = sigmoid( h2 @ W3[:,j] + b3[j] ), j in [0,1024).
    {
        float s = b3[tid];
        const float* w = W3 + tid;
#pragma unroll 20
        for (int i = 0; i < HID; i++)
            s += s_h2[i] * __ldg(&w[(size_t)i * (RB * CB)]);
        out[tid] = 1.0f / (1.0f + expf(-s));
    }

    // Pack cumsums (as f32) after the 1024 propensity values.
    if (tid <= RB)  out[RB * CB + tid] = (float)s_rcum[tid];
    if (tid <= CB)  out[RB * CB + (RB + 1) + tid] = (float)s_ccum[tid];
}

// ---------------------------------------------------------------------------
// Launch
// ---------------------------------------------------------------------------
extern "C" void kernel_launch(void* const* d_in, const int* in_sizes, int n_in,
                              void* d_out, int out_size) {
    const float* X       = (const float*)d_in[0];
    const int*   row_ids = (const int*)d_in[1];
    const int*   col_ids = (const int*)d_in[2];
    const float* W1 = (const float*)d_in[3];
    const float* b1 = (const float*)d_in[4];
    const float* W2 = (const float*)d_in[5];
    const float* b2 = (const float*)d_in[6];
    const float* W3 = (const float*)d_in[7];
    const float* b3 = (const float*)d_in[8];
    float* out = (float*)d_out;

    dim3 grid(NCOLS / STRIP_COLS, NROWS / ROWS_PER_CTA);   // (16, 64)
    mar_reduce_kernel<<<grid, THREADS_RED>>>(X, row_ids, col_ids);

    mar_finalize_kernel<<<1, 1024>>>(row_ids, col_ids,
                                     W1, b1, W2, b2, W3, b3, out);
}

// round 4
// speedup vs baseline: 1.9127x; 1.5581x over previous
#include <cuda_runtime.h>
#include <math.h>

#define NROWS 8192
#define NCOLS 8192
#define RB 32
#define CB 32
#define HID 100
#define DIO (RB * CB)                  // 1024
#define ROWS_PER_CTA 128
#define THREADS_RED 128
#define STRIP_COLS (THREADS_RED * 4)   // 512 columns per CTA strip
#define ST_V4 (NCOLS / 4)              // float4 row stride
#define MAXRUNS 33

// Device-global scratch (no allocations allowed). Accumulators (g_blk, g_h1)
// start zero and are re-zeroed by downstream kernels after being consumed, so
// every graph replay sees a clean state. g_h2/g_rcum/g_ccum are fully
// overwritten each replay.
__device__ float g_blk[DIO];
__device__ float g_h1[HID];
__device__ float g_h2[HID];
__device__ int   g_rcum[RB + 1];
__device__ int   g_ccum[CB + 1];

__device__ __forceinline__ int lb_count_less(const int* __restrict__ a,
                                             int n, int key) {
    int lo = 0, hi = n;
    while (lo < hi) {
        int mid = (lo + hi) >> 1;
        if (__ldg(&a[mid]) < key) lo = mid + 1; else hi = mid;
    }
    return lo;
}

// ---------------------------------------------------------------------------
// Kernel 1: segmented block-sum reduce of X (HBM-bound, ~99.9% of bytes).
// Grid (16, 64) = 1024 CTAs x 128 thr. Run-based branch-free hot loop with
// 8 front-batched float4 streaming loads (MLP ~ 8 per warp).
// CTA (0,0) additionally computes the cumsums (independent of X) and writes
// them to g_rcum/g_ccum and the tail of `out` — hidden under the reduce.
// ---------------------------------------------------------------------------
__global__ __launch_bounds__(THREADS_RED)
void mar_reduce_kernel(const float* __restrict__ X,
                       const int* __restrict__ row_ids,
                       const int* __restrict__ col_ids,
                       float* __restrict__ out) {
    __shared__ float s_blk[DIO];
    __shared__ unsigned char s_rseg[ROWS_PER_CTA];
    __shared__ short s_run_start[MAXRUNS + 1];
    __shared__ unsigned char s_run_seg[MAXRUNS];
    __shared__ int s_nrun;

    const int tid = threadIdx.x;
    const int r0 = blockIdx.y * ROWS_PER_CTA;
    const int c0 = blockIdx.x * STRIP_COLS + tid * 4;

    for (int i = tid; i < DIO; i += THREADS_RED) s_blk[i] = 0.0f;
    if (tid < ROWS_PER_CTA)
        s_rseg[tid] = (unsigned char)row_ids[r0 + tid];

    const int cs0 = col_ids[c0 + 0];
    const int cs1 = col_ids[c0 + 1];
    const int cs2 = col_ids[c0 + 2];
    const int cs3 = col_ids[c0 + 3];
    __syncthreads();

    // Build run list (sorted ids -> typically 1-2 runs per 128-row chunk).
    if (tid == 0) {
        int n = 0, prev = -1;
        for (int r = 0; r < ROWS_PER_CTA; r++) {
            int s = s_rseg[r];
            if (s != prev) {
                s_run_start[n] = (short)r;
                s_run_seg[n] = (unsigned char)s;
                n++; prev = s;
            }
        }
        s_run_start[n] = ROWS_PER_CTA;
        s_nrun = n;
    }
    __syncthreads();

    const float4* __restrict__ p = (const float4*)(X + (size_t)r0 * NCOLS + c0);
    const int nrun = s_nrun;

    for (int run = 0; run < nrun; run++) {
        const int rs = s_run_start[run];
        const int re = s_run_start[run + 1];
        const int seg = s_run_seg[run];
        const float4* __restrict__ q = p + (size_t)rs * ST_V4;
        const int n = re - rs;

        float a0 = 0.f, a1 = 0.f, a2 = 0.f, a3 = 0.f;
        int r = 0;
        for (; r + 8 <= n; r += 8) {
            float4 v0 = __ldcs(&q[(size_t)(r + 0) * ST_V4]);
            float4 v1 = __ldcs(&q[(size_t)(r + 1) * ST_V4]);
            float4 v2 = __ldcs(&q[(size_t)(r + 2) * ST_V4]);
            float4 v3 = __ldcs(&q[(size_t)(r + 3) * ST_V4]);
            float4 v4 = __ldcs(&q[(size_t)(r + 4) * ST_V4]);
            float4 v5 = __ldcs(&q[(size_t)(r + 5) * ST_V4]);
            float4 v6 = __ldcs(&q[(size_t)(r + 6) * ST_V4]);
            float4 v7 = __ldcs(&q[(size_t)(r + 7) * ST_V4]);
            a0 += v0.x; a1 += v0.y; a2 += v0.z; a3 += v0.w;
            a0 += v1.x; a1 += v1.y; a2 += v1.z; a3 += v1.w;
            a0 += v2.x; a1 += v2.y; a2 += v2.z; a3 += v2.w;
            a0 += v3.x; a1 += v3.y; a2 += v3.z; a3 += v3.w;
            a0 += v4.x; a1 += v4.y; a2 += v4.z; a3 += v4.w;
            a0 += v5.x; a1 += v5.y; a2 += v5.z; a3 += v5.w;
            a0 += v6.x; a1 += v6.y; a2 += v6.z; a3 += v6.w;
            a0 += v7.x; a1 += v7.y; a2 += v7.z; a3 += v7.w;
        }
        for (; r < n; r++) {
            float4 v = __ldcs(&q[(size_t)r * ST_V4]);
            a0 += v.x; a1 += v.y; a2 += v.z; a3 += v.w;
        }
        const int base = seg * CB;
        atomicAdd(&s_blk[base + cs0], a0);
        atomicAdd(&s_blk[base + cs1], a1);
        atomicAdd(&s_blk[base + cs2], a2);
        atomicAdd(&s_blk[base + cs3], a3);
    }
    __syncthreads();

    for (int i = tid; i < DIO; i += THREADS_RED) {
        float v = s_blk[i];
        if (v != 0.0f) atomicAdd(&g_blk[i], v);
    }

    // Side task (one CTA): cumsums via lower_bound on sorted ids.
    if (blockIdx.x == 0 && blockIdx.y == 0) {
        if (tid <= RB) {
            int v = lb_count_less(row_ids, NROWS, tid);
            g_rcum[tid] = v;
            out[DIO + tid] = (float)v;
        } else if (tid < 2 * (RB + 1)) {
            int t = tid - (RB + 1);
            int v = lb_count_less(col_ids, NCOLS, t);
            g_ccum[t] = v;
            out[DIO + (RB + 1) + t] = (float)v;
        }
    }
}

// ---------------------------------------------------------------------------
// Kernel 2: Layer 1 partials, grid 8 x 256. CTA c handles input rows
// [c*128, (c+1)*128); block-mean computed on the fly; partial dot products
// atomically accumulated into g_h1 (init 0; bias added in kernel 3).
// ---------------------------------------------------------------------------
__global__ __launch_bounds__(256)
void mar_l1_kernel(const float* __restrict__ W1) {
    __shared__ float s_x[128];
    const int tid = threadIdx.x;
    const int i0 = blockIdx.x * 128;

    if (tid < 128) {
        int i = i0 + tid;
        int ri = i >> 5, ci = i & 31;
        float rc = (float)(g_rcum[ri + 1] - g_rcum[ri]);
        float cc = (float)(g_ccum[ci + 1] - g_ccum[ci]);
        s_x[tid] = g_blk[i] / fmaxf(rc * cc, 1.0f);
    }
    __syncthreads();

    const int half = tid >> 7;        // 0 or 1: 64 input rows each
    const int k = tid & 127;
    if (k < HID) {
        float s = 0.0f;
        const float* __restrict__ w = W1 + (size_t)(i0 + half * 64) * HID + k;
        const float* __restrict__ xs = s_x + half * 64;
#pragma unroll 16
        for (int i = 0; i < 64; i++)
            s += xs[i] * __ldg(&w[(size_t)i * HID]);
        atomicAdd(&g_h1[k], s);
    }
}

// ---------------------------------------------------------------------------
// Kernel 3: relu(h1 + b1) -> Layer 2 (100x100) -> g_h2.
// Also self-cleans the accumulators (g_h1, g_blk) for the next replay.
// ---------------------------------------------------------------------------
__global__ __launch_bounds__(128)
void mar_l2_kernel(const float* __restrict__ b1,
                   const float* __restrict__ W2,
                   const float* __restrict__ b2) {
    __shared__ float s_h1[HID];
    const int tid = threadIdx.x;

    if (tid < HID) {
        s_h1[tid] = fmaxf(g_h1[tid] + b1[tid], 0.0f);
        g_h1[tid] = 0.0f;                 // consumed -> clean for next replay
    }
    for (int i = tid; i < DIO; i += 128)  // g_blk consumed by kernel 2
        g_blk[i] = 0.0f;
    __syncthreads();

    if (tid < HID) {
        float s = b2[tid];
        const float* __restrict__ w = W2 + tid;
#pragma unroll 20
        for (int i = 0; i < HID; i++)
            s += s_h1[i] * __ldg(&w[(size_t)i * HID]);
        g_h2[tid] = fmaxf(s, 0.0f);       // full overwrite, no cleaning needed
    }
}

// ---------------------------------------------------------------------------
// Kernel 4: Layer 3 + sigmoid, grid 8 x 128. CTA c writes out[c*128 ...].
// W3 columns: consecutive threads -> consecutive addresses (coalesced).
// ---------------------------------------------------------------------------
__global__ __launch_bounds__(128)
void mar_l3_kernel(const float* __restrict__ W3,
                   const float* __restrict__ b3,
                   float* __restrict__ out) {
    __shared__ float s_h2[HID];
    const int tid = threadIdx.x;
    if (tid < HID) s_h2[tid] = g_h2[tid];
    __syncthreads();

    const int j = blockIdx.x * 128 + tid;
    float s = b3[j];
    const float* __restrict__ w = W3 + j;
#pragma unroll 20
    for (int i = 0; i < HID; i++)
        s += s_h2[i] * __ldg(&w[(size_t)i * DIO]);
    out[j] = 1.0f / (1.0f + expf(-s));
}

// ---------------------------------------------------------------------------
// Launch
// ---------------------------------------------------------------------------
extern "C" void kernel_launch(void* const* d_in, const int* in_sizes, int n_in,
                              void* d_out, int out_size) {
    const float* X       = (const float*)d_in[0];
    const int*   row_ids = (const int*)d_in[1];
    const int*   col_ids = (const int*)d_in[2];
    const float* W1 = (const float*)d_in[3];
    const float* b1 = (const float*)d_in[4];
    const float* W2 = (const float*)d_in[5];
    const float* b2 = (const float*)d_in[6];
    const float* W3 = (const float*)d_in[7];
    const float* b3 = (const float*)d_in[8];
    float* out = (float*)d_out;

    dim3 grid(NCOLS / STRIP_COLS, NROWS / ROWS_PER_CTA);   // (16, 64)
    mar_reduce_kernel<<<grid, THREADS_RED>>>(X, row_ids, col_ids, out);

    mar_l1_kernel<<<8, 256>>>(W1);
    mar_l2_kernel<<<1, 128>>>(b1, W2, b2);
    mar_l3_kernel<<<8, 128>>>(W3, b3, out);
}